// round 14
// baseline (speedup 1.0000x reference)
#include <cuda_runtime.h>
#include <cuda_bf16.h>
#include <math.h>
#include <string.h>

#define N_ENT  40943
#define RANKD  500
#define BATCH  1024
#define INSZ   600
#define GK     1000
#define KQ     3072      /* A' split-K : [hi | lo | hi], 1024 each */
#define KB     2048      /* B' width   : [hi | lo],     1024 each */
#define SCALE  0.04472135954999579f   /* 1/sqrt(500) */
#define NSPLIT 4

// ---------------- scratch (static device globals; no allocation) ----------
static __device__ float g_t1p[NSPLIT * BATCH * RANKD];
static __device__ float g_t2p[NSPLIT * BATCH * RANKD];
static __device__ float g_t2[BATCH * RANKD];
static __device__ float g_t3p[NSPLIT * BATCH * RANKD];
static __device__ __align__(16) __nv_bfloat16 g_Aq[BATCH * KQ];
static __device__ __align__(16) __nv_bfloat16 g_Bq[(size_t)N_ENT * KB];

// ---------------- helpers --------------------------------------------------
__device__ __forceinline__ float softplusf(float x) {
    return fmaxf(x, 0.f) + log1pf(expf(-fabsf(x)));
}
__device__ __forceinline__ float artanh_clipf(float x) {
    x = fminf(fmaxf(x, -1.f + 1e-5f), 1.f - 1e-5f);
    return 0.5f * (log1pf(x) - log1pf(-x));
}
__device__ __forceinline__ unsigned smem_u32(const void* p) {
    unsigned r;
    asm("{ .reg .u64 t; cvta.to.shared.u64 t, %1; cvt.u32.u64 %0, t; }"
        : "=r"(r) : "l"(p));
    return r;
}

#define CP16(dst, src) \
    asm volatile("cp.async.cg.shared.global [%0], [%1], 16;" \
                 :: "r"(dst), "l"(src) : "memory")
#define CP_COMMIT() asm volatile("cp.async.commit_group;" ::: "memory")
#define CP_WAIT1()  asm volatile("cp.async.wait_group 1;" ::: "memory")

#define LDSM4(r0, r1, r2, r3, addr) \
    asm volatile("ldmatrix.sync.aligned.m8n8.x4.shared.b16 {%0,%1,%2,%3}, [%4];" \
                 : "=r"(r0), "=r"(r1), "=r"(r2), "=r"(r3) : "r"(addr))

#define MMA16816(c, a, b0, b1) \
    asm volatile("mma.sync.aligned.m16n8k16.row.col.f32.bf16.bf16.f32 " \
                 "{%0,%1,%2,%3},{%4,%5,%6,%7},{%8,%9},{%0,%1,%2,%3};" \
                 : "+f"((c)[0]), "+f"((c)[1]), "+f"((c)[2]), "+f"((c)[3]) \
                 : "r"((a)[0]), "r"((a)[1]), "r"((a)[2]), "r"((a)[3]), \
                   "r"(b0), "r"(b1))

// ---------------- fc1 split-K: X = pos[h]*pvw[h]*scale built on the fly ----
__global__ void fc1_split_kernel(const int* __restrict__ x,
                                 const float* __restrict__ pos,
                                 const float* __restrict__ pvw,
                                 const float* __restrict__ W,
                                 float* __restrict__ Cp) {
    const int z = blockIdx.z;
    const int kb = z * (INSZ / NSPLIT), ke = kb + INSZ / NSPLIT;
    __shared__ float Xs[16][32];
    __shared__ float Ws[16][64];
    __shared__ int sh_h[32];
    const int tid = threadIdx.x;
    const int tx = tid & 15, ty = tid >> 4;
    const int bm = blockIdx.y * 32, bn = blockIdx.x * 64;
    float acc[4][4] = {};

    if (tid < 32) sh_h[tid] = x[(bm + tid) * 3];
    __syncthreads();

    const int xl_row = tid & 31, xl_k = (tid >> 5) * 4;
    const int wl_row = tid & 63, wl_k = (tid >> 6) * 8;
    const int hrow = sh_h[xl_row];
    const int ng_w = bn + wl_row;

    for (int k0 = kb; k0 < ke; k0 += 16) {
#pragma unroll
        for (int i = 0; i < 4; i++) {
            int kg = k0 + xl_k + i;
            Xs[xl_k + i][xl_row] = (kg < ke)
                ? pos[(size_t)hrow * INSZ + kg] * pvw[(size_t)hrow * INSZ + kg] * SCALE
                : 0.f;
        }
#pragma unroll
        for (int i = 0; i < 8; i++) {
            int kg = k0 + wl_k + i;
            Ws[wl_k + i][wl_row] = (kg < ke && ng_w < RANKD)
                ? W[(size_t)ng_w * INSZ + kg] : 0.f;
        }
        __syncthreads();
#pragma unroll
        for (int kk = 0; kk < 16; kk++) {
            float a[4], b[4];
#pragma unroll
            for (int i = 0; i < 4; i++) a[i] = Xs[kk][ty * 4 + i];
#pragma unroll
            for (int j = 0; j < 4; j++) b[j] = Ws[kk][tx * 4 + j];
#pragma unroll
            for (int i = 0; i < 4; i++)
#pragma unroll
                for (int j = 0; j < 4; j++) acc[i][j] += a[i] * b[j];
        }
        __syncthreads();
    }
    float* out = Cp + (size_t)z * BATCH * RANKD;
#pragma unroll
    for (int i = 0; i < 4; i++) {
        int mg = bm + ty * 4 + i;
#pragma unroll
        for (int j = 0; j < 4; j++) {
            int ng = bn + tx * 4 + j;
            if (ng < RANKD) out[(size_t)mg * RANKD + ng] = acc[i][j];
        }
    }
}

// ---------------- fc2 split-K: X = sum4(t1p) + fc1_b ; K=500 split 4x125 ---
__global__ void fc2_split_kernel(const float* __restrict__ Xp,
                                 const float* __restrict__ xbias,
                                 const float* __restrict__ W,
                                 float* __restrict__ Cp) {
    const int z = blockIdx.z;
    const int kb = z * (RANKD / NSPLIT), ke = kb + RANKD / NSPLIT;
    __shared__ float Xs[16][32];
    __shared__ float Ws[16][64];
    const int tid = threadIdx.x;
    const int tx = tid & 15, ty = tid >> 4;
    const int bm = blockIdx.y * 32, bn = blockIdx.x * 64;
    float acc[4][4] = {};

    const int xl_row = tid & 31, xl_k = (tid >> 5) * 4;
    const int wl_row = tid & 63, wl_k = (tid >> 6) * 8;
    const int mg_x = bm + xl_row;
    const int ng_w = bn + wl_row;

    for (int k0 = kb; k0 < ke; k0 += 16) {
#pragma unroll
        for (int i = 0; i < 4; i++) {
            int kg = k0 + xl_k + i;
            float v = 0.f;
            if (kg < ke) {
                size_t idx = (size_t)mg_x * RANKD + kg;
                v = Xp[idx] + Xp[idx + (size_t)BATCH * RANKD]
                  + Xp[idx + (size_t)2 * BATCH * RANKD]
                  + Xp[idx + (size_t)3 * BATCH * RANKD] + xbias[kg];
            }
            Xs[xl_k + i][xl_row] = v;
        }
#pragma unroll
        for (int i = 0; i < 8; i++) {
            int kg = k0 + wl_k + i;
            Ws[wl_k + i][wl_row] = (kg < ke && ng_w < RANKD)
                ? W[(size_t)ng_w * RANKD + kg] : 0.f;
        }
        __syncthreads();
#pragma unroll
        for (int kk = 0; kk < 16; kk++) {
            float a[4], b[4];
#pragma unroll
            for (int i = 0; i < 4; i++) a[i] = Xs[kk][ty * 4 + i];
#pragma unroll
            for (int j = 0; j < 4; j++) b[j] = Ws[kk][tx * 4 + j];
#pragma unroll
            for (int i = 0; i < 4; i++)
#pragma unroll
                for (int j = 0; j < 4; j++) acc[i][j] += a[i] * b[j];
        }
        __syncthreads();
    }
    float* out = Cp + (size_t)z * BATCH * RANKD;
#pragma unroll
    for (int i = 0; i < 4; i++) {
        int mg = bm + ty * 4 + i;
#pragma unroll
        for (int j = 0; j < 4; j++) {
            int ng = bn + tx * 4 + j;
            if (ng < RANKD) out[(size_t)mg * RANKD + ng] = acc[i][j];
        }
    }
}

// ---------------- fc3 split-K: X = g_t2 (plain) ; K=500 split 4x125 --------
__global__ void fc3_split_kernel(const float* __restrict__ X,
                                 const float* __restrict__ W,
                                 float* __restrict__ Cp) {
    const int z = blockIdx.z;
    const int kb = z * (RANKD / NSPLIT), ke = kb + RANKD / NSPLIT;
    __shared__ float Xs[16][32];
    __shared__ float Ws[16][64];
    const int tid = threadIdx.x;
    const int tx = tid & 15, ty = tid >> 4;
    const int bm = blockIdx.y * 32, bn = blockIdx.x * 64;
    float acc[4][4] = {};

    const int xl_row = tid & 31, xl_k = (tid >> 5) * 4;
    const int wl_row = tid & 63, wl_k = (tid >> 6) * 8;
    const int mg_x = bm + xl_row;
    const int ng_w = bn + wl_row;

    for (int k0 = kb; k0 < ke; k0 += 16) {
#pragma unroll
        for (int i = 0; i < 4; i++) {
            int kg = k0 + xl_k + i;
            Xs[xl_k + i][xl_row] = (kg < ke) ? X[(size_t)mg_x * RANKD + kg] : 0.f;
        }
#pragma unroll
        for (int i = 0; i < 8; i++) {
            int kg = k0 + wl_k + i;
            Ws[wl_k + i][wl_row] = (kg < ke && ng_w < RANKD)
                ? W[(size_t)ng_w * RANKD + kg] : 0.f;
        }
        __syncthreads();
#pragma unroll
        for (int kk = 0; kk < 16; kk++) {
            float a[4], b[4];
#pragma unroll
            for (int i = 0; i < 4; i++) a[i] = Xs[kk][ty * 4 + i];
#pragma unroll
            for (int j = 0; j < 4; j++) b[j] = Ws[kk][tx * 4 + j];
#pragma unroll
            for (int i = 0; i < 4; i++)
#pragma unroll
                for (int j = 0; j < 4; j++) acc[i][j] += a[i] * b[j];
        }
        __syncthreads();
    }
    float* out = Cp + (size_t)z * BATCH * RANKD;
#pragma unroll
    for (int i = 0; i < 4; i++) {
        int mg = bm + ty * 4 + i;
#pragma unroll
        for (int j = 0; j < 4; j++) {
            int ng = bn + tx * 4 + j;
            if (ng < RANKD) out[(size_t)mg * RANKD + ng] = acc[i][j];
        }
    }
}

// ---------------- LayerNorm: sum 4 partials + fc2_b, normalize -> g_t2 -----
__global__ void ln_sum_kernel(const float* __restrict__ xbias,
                              const float* __restrict__ g,
                              const float* __restrict__ bta) {
    int row = blockIdx.x;
    const size_t base = (size_t)row * RANKD;
    const size_t stride = (size_t)BATCH * RANKD;
    __shared__ float s1[128], s2[128];
    __shared__ float vals[RANKD];
    float sum = 0.f, ss = 0.f;
    for (int d = threadIdx.x; d < RANKD; d += 128) {
        float v = g_t2p[base + d] + g_t2p[base + d + stride]
                + g_t2p[base + d + 2 * stride] + g_t2p[base + d + 3 * stride]
                + xbias[d];
        vals[d] = v;
        sum += v;
        ss += v * v;
    }
    s1[threadIdx.x] = sum;
    s2[threadIdx.x] = ss;
    __syncthreads();
    for (int s = 64; s > 0; s >>= 1) {
        if (threadIdx.x < s) {
            s1[threadIdx.x] += s1[threadIdx.x + s];
            s2[threadIdx.x] += s2[threadIdx.x + s];
        }
        __syncthreads();
    }
    float mu = s1[0] / RANKD;
    float var = s2[0] / RANKD - mu * mu;
    float rstd = rsqrtf(fmaxf(var, 0.f) + 1e-5f);
    for (int d = threadIdx.x; d < RANKD; d += 128)
        g_t2[base + d] = (vals[d] - mu) * rstd * g[d] + bta[d];
}

// ---------------- fused per-batch kernel: writes g_Aq = [hi|lo|hi] ---------
__global__ void fuse_kernel(const int* __restrict__ x, const int* __restrict__ nbrs,
                            const float* __restrict__ emb_e, const float* __restrict__ emb_r,
                            const float* __restrict__ emb1_r, const float* __restrict__ ctxv,
                            const float* __restrict__ nvw,
                            const float* __restrict__ c1_p, const float* __restrict__ c2_p,
                            const float* __restrict__ ab_p,
                            const float* __restrict__ mn_w, const float* __restrict__ mn_b,
                            const float* __restrict__ fc3_b) {
    const int b = blockIdx.x;
    const int tid = threadIdx.x;
    __shared__ int sh_idx[12];
    __shared__ float red[5][128];
    __shared__ float sh_lhs[RANKD];
    __shared__ float sh_rot[RANKD];
    __shared__ float shS[12];

    if (tid == 0) {
        int h = x[b * 3], r = x[b * 3 + 1];
        sh_idx[0] = h;
        sh_idx[1] = r;
        for (int j = 0; j < 5; j++) {
            sh_idx[2 + j] = nbrs[(h * 5 + j) * 2];
            sh_idx[7 + j] = nbrs[(h * 5 + j) * 2 + 1];
        }
    }
    __syncthreads();
    const int h = sh_idx[0], r = sh_idx[1];

    float pj[5] = {0, 0, 0, 0, 0};
    for (int d = tid; d < RANKD; d += 128) {
#pragma unroll
        for (int j = 0; j < 5; j++) {
            int rel = sh_idx[7 + j];
            pj[j] += nvw[rel * RANKD + d] * emb_r[rel * GK + d];
        }
    }
#pragma unroll
    for (int j = 0; j < 5; j++) red[j][tid] = pj[j];
    __syncthreads();
    for (int s = 64; s > 0; s >>= 1) {
        if (tid < s) {
#pragma unroll
            for (int j = 0; j < 5; j++) red[j][tid] += red[j][tid + s];
        }
        __syncthreads();
    }
    if (tid == 0) {
        float l[5], mx = -1e30f;
        for (int j = 0; j < 5; j++) {
            l[j] = red[j][0] * SCALE;
            mx = fmaxf(mx, l[j]);
        }
        float se = 0.f;
        for (int j = 0; j < 5; j++) {
            l[j] = expf(l[j] - mx);
            se += l[j];
        }
        float ab = 0.f;
        for (int j = 0; j < 5; j++) {
            shS[j] = l[j] / se;
            ab += softplusf(ab_p[sh_idx[7 + j]]);
        }
        shS[5] = ab * 0.2f;
        shS[6] = softplusf(mn_w[r] + mn_b[0]);
        shS[7] = sqrtf(softplusf(c1_p[r]));
        shS[8] = sqrtf(softplusf(c2_p[r]));
    }
    __syncthreads();

    float ss = 0.f;
    {
        float ab = shS[5], mn = shS[6];
        const size_t base = (size_t)b * RANKD;
        const size_t stride = (size_t)BATCH * RANKD;
        for (int d = tid; d < RANKD; d += 128) {
            float att = 0.f;
#pragma unroll
            for (int j = 0; j < 5; j++) att += shS[j] * emb_e[sh_idx[2 + j] * GK + d];
            float t3 = g_t3p[base + d] + g_t3p[base + d + stride]
                     + g_t3p[base + d + 2 * stride] + g_t3p[base + d + 3 * stride]
                     + fc3_b[d];
            float v = emb_e[h * GK + d] + ab * att + mn * t3;
            sh_lhs[d] = v;
            ss += v * v;
        }
    }
    red[0][tid] = ss;
    __syncthreads();
    for (int s = 64; s > 0; s >>= 1) {
        if (tid < s) red[0][tid] += red[0][tid + s];
        __syncthreads();
    }
    if (tid == 0) {
        float sc1 = shS[7], sc2 = shS[8];
        float n = sqrtf(red[0][0]);
        float un = fmaxf(n, 1e-15f);
        float t1h = tanhf(sc1 * un);
        float f1 = t1h / (sc1 * un);
        float gn = fmaxf(f1 * n, 1e-15f);
        float mx1 = 0.996f / sc1;
        float pf1 = (gn > mx1) ? (mx1 / gn) : 1.f;
        float h1s = pf1 * f1;
        float yn1 = h1s * n;
        float un2 = fmaxf(yn1, 1e-15f);
        float t2h = tanhf(sc2 * un2);
        float f2 = t2h / (sc2 * un2);
        float gn2 = fmaxf(f2 * yn1, 1e-15f);
        float mx2 = 0.996f / sc2;
        float pf2 = (gn2 > mx2) ? (mx2 / gn2) : 1.f;
        float beta = pf2 * f2;
        float yn2 = beta * yn1;
        float y1 = fmaxf(yn1, 1e-15f);
        float a1 = artanh_clipf(sc1 * y1) / (y1 * sc1);
        float y2 = fmaxf(yn2, 1e-15f);
        float a2 = artanh_clipf(sc2 * y2) / (y2 * sc2);
        shS[9] = h1s;
        shS[10] = a1;
        shS[11] = a2 * beta;
    }
    __syncthreads();

    float pd = 0.f;
    {
        float h1s = shS[9];
        for (int q = tid; q < RANKD / 2; q += 128) {
            float g0 = emb1_r[r * GK + 2 * q];
            float g1 = emb1_r[r * GK + 2 * q + 1];
            float gg = fmaxf(sqrtf(g0 * g0 + g1 * g1), 1e-15f);
            g0 /= gg;
            g1 /= gg;
            float x0 = h1s * sh_lhs[2 * q];
            float x1 = h1s * sh_lhs[2 * q + 1];
            float r0 = g0 * x0 - g1 * x1;
            float r1 = g0 * x1 + g1 * x0;
            sh_rot[2 * q] = r0;
            sh_rot[2 * q + 1] = r1;
            pd += ctxv[r * RANKD + 2 * q] * r0 + ctxv[r * RANKD + 2 * q + 1] * r1;
        }
    }
    red[0][tid] = pd;
    __syncthreads();
    for (int s = 64; s > 0; s >>= 1) {
        if (tid < s) red[0][tid] += red[0][tid + s];
        __syncthreads();
    }
    if (tid == 0) {
        float d0 = red[0][0] * SCALE;
        float s1 = shS[10], s2 = shS[11];
        float l0 = s1 * d0, l1 = s2 * d0, l2 = d0;
        float mx = fmaxf(l0, fmaxf(l1, l2));
        float e0 = expf(l0 - mx), e1 = expf(l1 - mx), e2 = expf(l2 - mx);
        float inv = 1.f / (e0 + e1 + e2);
        shS[0] = (e0 * s1 + e1 * s2 + e2) * inv;
    }
    __syncthreads();

    // Phase D: write A' row directly (hi | lo | hi), bf16, pad tails = 0
    {
        float S = shS[0];
        __nv_bfloat16* dst = g_Aq + (size_t)b * KQ;
        for (int d = tid; d < RANKD; d += 128) {
            float aq = S * sh_rot[d];
            float l1v = emb_e[h * GK + RANKD + d];
            float r0v = emb_r[r * GK + d];
            float rbv = emb_r[r * GK + RANKD + d];
            float A0 = aq * r0v - l1v * rbv;
            float A1 = aq * rbv + l1v * r0v;
            __nv_bfloat16 h0 = __float2bfloat16(A0);
            __nv_bfloat16 h1 = __float2bfloat16(A1);
            __nv_bfloat16 lo0 = __float2bfloat16(A0 - __bfloat162float(h0));
            __nv_bfloat16 lo1 = __float2bfloat16(A1 - __bfloat162float(h1));
            dst[d] = h0;             dst[RANKD + d] = h1;
            dst[1024 + d] = lo0;     dst[1024 + RANKD + d] = lo1;
            dst[2048 + d] = h0;      dst[2048 + RANKD + d] = h1;
        }
        if (tid < 24) {
            __nv_bfloat16 z = __float2bfloat16(0.f);
            dst[1000 + tid] = z;
            dst[2024 + tid] = z;
            dst[3048 + tid] = z;
        }
    }
}

// ---------------- conversion: B' = [hi | lo] bf16 of emb_e -----------------
__global__ void convB_kernel(const float* __restrict__ emb_e) {
    int n = blockIdx.x;
    const float* src = emb_e + (size_t)n * GK;
    __nv_bfloat162* dh = (__nv_bfloat162*)(g_Bq + (size_t)n * KB);
    __nv_bfloat162* dl = dh + 512;
    for (int p = threadIdx.x; p < 512; p += 128) {
        int k = 2 * p;
        float a = (k < GK) ? src[k] : 0.f;
        float b = (k + 1 < GK) ? src[k + 1] : 0.f;
        __nv_bfloat16 ah = __float2bfloat16(a);
        __nv_bfloat16 bh = __float2bfloat16(b);
        __nv_bfloat16 al = __float2bfloat16(a - __bfloat162float(ah));
        __nv_bfloat16 bl = __float2bfloat16(b - __bfloat162float(bh));
        dh[p] = __halves2bfloat162(ah, bh);
        dl[p] = __halves2bfloat162(al, bl);
    }
}

// ---------------- big GEMM via mma.sync bf16 -------------------------------
// R11 winner + single-barrier mainloop (WAR across NSTG=3 slots is ordered
// by the start-of-iteration barrier; end barrier removed).
#define NSTG      3
#define STG_BYT   32768          /* A 16KB + B 16KB */
#define SMEM_GEMM (NSTG * STG_BYT)
#define KSTAGES   (KQ / 64)      /* 48 */

__global__ void __launch_bounds__(256, 2)
big_gemm_mma(float* __restrict__ C) {
    extern __shared__ __align__(1024) char smem[];
    const unsigned sb = smem_u32(smem);
    const int tid = threadIdx.x;
    const int wid = tid >> 5, lane = tid & 31;
    const int bm = blockIdx.y * 128;
    const int bn = blockIdx.x * 128;
    const int wm = wid >> 2;          // 0..1
    const int wn = wid & 3;           // 0..3

    auto load_stage = [&](int st) {
        const unsigned abase = sb + (unsigned)(st % NSTG) * STG_BYT;
        const unsigned bbase = abase + 16384u;
        const int k0 = st * 64;
        const int bk = (k0 < 1024) ? k0 : k0 - 1024;   // hi.hi | lo.hi | hi.lo
#pragma unroll
        for (int i = 0; i < 4; i++) {
            int q = tid + 256 * i;
            int row = q >> 3, c = q & 7;
            unsigned dst = abase + (unsigned)(row * 128 + ((c ^ (row & 7)) << 4));
            const void* src = g_Aq + (size_t)(bm + row) * KQ + k0 + c * 8;
            CP16(dst, src);
        }
#pragma unroll
        for (int i = 0; i < 4; i++) {
            int q = tid + 256 * i;
            int row = q >> 3, c = q & 7;
            int gr = bn + row;
            if (gr >= N_ENT) gr = 0;
            unsigned dst = bbase + (unsigned)(row * 128 + ((c ^ (row & 7)) << 4));
            const void* src = g_Bq + (size_t)gr * KB + bk + c * 8;
            CP16(dst, src);
        }
    };

    float acc[4][4][4];
#pragma unroll
    for (int i = 0; i < 4; i++)
#pragma unroll
        for (int j = 0; j < 4; j++)
#pragma unroll
            for (int v = 0; v < 4; v++) acc[i][j][v] = 0.f;

    load_stage(0); CP_COMMIT();
    load_stage(1); CP_COMMIT();

    const int a_row_l = lane & 15;
    const int a_ch_l  = lane >> 4;
    const int b_row_l = (lane & 7) + ((lane >> 4) << 3);
    const int b_ch_l  = (lane >> 3) & 1;

    for (int kb = 0; kb < KSTAGES; ++kb) {
        CP_WAIT1();
        __syncthreads();          // orders prev-iter reads before this iter's
                                  // writes into slot (kb+2)%3 == slot(kb-1)
        if (kb + 2 < KSTAGES) load_stage(kb + 2);
        CP_COMMIT();

        const unsigned abase = sb + (unsigned)(kb % NSTG) * STG_BYT;
        const unsigned bbase = abase + 16384u;

#pragma unroll
        for (int k16 = 0; k16 < 4; ++k16) {
            unsigned a[4][4];
#pragma unroll
            for (int fi = 0; fi < 4; ++fi) {
                int row = wm * 64 + fi * 16 + a_row_l;
                int ch = k16 * 2 + a_ch_l;
                unsigned addr = abase + (unsigned)(row * 128 + ((ch ^ (row & 7)) << 4));
                LDSM4(a[fi][0], a[fi][1], a[fi][2], a[fi][3], addr);
            }
            unsigned b[4][2];
#pragma unroll
            for (int bj = 0; bj < 2; ++bj) {
                int row = wn * 32 + bj * 16 + b_row_l;
                int ch = k16 * 2 + b_ch_l;
                unsigned addr = bbase + (unsigned)(row * 128 + ((ch ^ (row & 7)) << 4));
                unsigned r0, r1, r2, r3;
                LDSM4(r0, r1, r2, r3, addr);
                b[2 * bj][0] = r0; b[2 * bj][1] = r1;
                b[2 * bj + 1][0] = r2; b[2 * bj + 1][1] = r3;
            }
#pragma unroll
            for (int fi = 0; fi < 4; ++fi)
#pragma unroll
                for (int fj = 0; fj < 4; ++fj)
                    MMA16816(acc[fi][fj], a[fi], b[fj][0], b[fj][1]);
        }
        // no end barrier: single-barrier pipeline
    }

    // scalar stores (N_ENT odd -> odd rows only 4B-aligned)
#pragma unroll
    for (int fi = 0; fi < 4; ++fi) {
        int r0 = bm + wm * 64 + fi * 16 + (lane >> 2);
        float* crow0 = C + (size_t)r0 * N_ENT;
        float* crow1 = crow0 + (size_t)8 * N_ENT;
#pragma unroll
        for (int fj = 0; fj < 4; ++fj) {
            int col = bn + wn * 32 + fj * 8 + (lane & 3) * 2;
            if (col + 1 < N_ENT) {
                crow0[col]     = acc[fi][fj][0];
                crow0[col + 1] = acc[fi][fj][1];
                crow1[col]     = acc[fi][fj][2];
                crow1[col + 1] = acc[fi][fj][3];
            } else if (col < N_ENT) {
                crow0[col] = acc[fi][fj][0];
                crow1[col] = acc[fi][fj][2];
            }
        }
    }
}

// ---------------- launch ----------------------------------------------------
extern "C" void kernel_launch(void* const* d_in, const int* in_sizes, int n_in,
                              void* d_out, int out_size) {
    const int* x = (const int*)d_in[0];
    const int* neighbors = (const int*)d_in[1];
    const float* position = (const float*)d_in[2];
    const float* emb_e = (const float*)d_in[3];
    const float* emb_r = (const float*)d_in[4];
    const float* emb1_r = (const float*)d_in[5];
    const float* context_vec = (const float*)d_in[6];
    const float* neighbor_vec_w = (const float*)d_in[7];
    const float* position_vec_w = (const float*)d_in[8];
    const float* c1_p = (const float*)d_in[9];
    const float* c2_p = (const float*)d_in[10];
    const float* ab_p = (const float*)d_in[11];
    const float* fc1_w = (const float*)d_in[12];
    const float* fc1_b = (const float*)d_in[13];
    const float* fc2_w = (const float*)d_in[14];
    const float* fc2_b = (const float*)d_in[15];
    const float* fc3_w = (const float*)d_in[16];
    const float* fc3_b = (const float*)d_in[17];
    const float* ln_g = (const float*)d_in[18];
    const float* ln_b = (const float*)d_in[19];
    const float* fc_mn_w = (const float*)d_in[20];
    const float* fc_mn_b = (const float*)d_in[21];
    float* out = (float*)d_out;

    cudaFuncSetAttribute(big_gemm_mma,
                         cudaFuncAttributeMaxDynamicSharedMemorySize, SMEM_GEMM);

    float *p_t1p, *p_t2p, *p_t2, *p_t3p;
    cudaGetSymbolAddress((void**)&p_t1p, g_t1p);
    cudaGetSymbolAddress((void**)&p_t2p, g_t2p);
    cudaGetSymbolAddress((void**)&p_t2, g_t2);
    cudaGetSymbolAddress((void**)&p_t3p, g_t3p);

    // one-time resources (creation only; identical graph every call)
    static cudaStream_t s2 = nullptr;
    static cudaEvent_t ev_fork = nullptr, ev_join = nullptr;
    if (s2 == nullptr) {
        cudaStreamCreateWithFlags(&s2, cudaStreamNonBlocking);
        cudaEventCreateWithFlags(&ev_fork, cudaEventDisableTiming);
        cudaEventCreateWithFlags(&ev_join, cudaEventDisableTiming);
    }

    // fork: convB (depends only on emb_e) overlaps the fc chain
    cudaEventRecord(ev_fork, 0);
    cudaStreamWaitEvent(s2, ev_fork, 0);
    convB_kernel<<<N_ENT, 128, 0, s2>>>(emb_e);
    cudaEventRecord(ev_join, s2);

    dim3 gsm((RANKD + 63) / 64, BATCH / 32, NSPLIT);
    fc1_split_kernel<<<gsm, 128>>>(x, position, position_vec_w, fc1_w, p_t1p);
    fc2_split_kernel<<<gsm, 128>>>(p_t1p, fc1_b, fc2_w, p_t2p);
    ln_sum_kernel<<<BATCH, 128>>>(fc2_b, ln_g, ln_b);
    fc3_split_kernel<<<gsm, 128>>>(p_t2, fc3_w, p_t3p);

    fuse_kernel<<<BATCH, 128>>>(x, neighbors, emb_e, emb_r, emb1_r, context_vec,
                                neighbor_vec_w, c1_p, c2_p, ab_p, fc_mn_w, fc_mn_b,
                                fc3_b);

    // join: big GEMM needs both A' (fuse, stream 0) and B' (convB, s2)
    cudaStreamWaitEvent(0, ev_join, 0);

    dim3 gbig((N_ENT + 127) / 128, BATCH / 128);
    big_gemm_mma<<<gbig, 256, SMEM_GEMM>>>(out);
}

// round 15
// speedup vs baseline: 1.0229x; 1.0229x over previous
#include <cuda_runtime.h>
#include <cuda_bf16.h>
#include <math.h>
#include <string.h>

#define N_ENT  40943
#define RANKD  500
#define BATCH  1024
#define INSZ   600
#define GK     1000
#define KQ     3072      /* A' split-K : [hi | lo | hi], 1024 each */
#define KB     2048      /* B' width   : [hi | lo],     1024 each */
#define SCALE  0.04472135954999579f   /* 1/sqrt(500) */
#define NSPLIT 4

// ---------------- scratch (static device globals; no allocation) ----------
static __device__ float g_t1p[NSPLIT * BATCH * RANKD];
static __device__ float g_t2p[NSPLIT * BATCH * RANKD];
static __device__ float g_t2[BATCH * RANKD];
static __device__ float g_t3p[NSPLIT * BATCH * RANKD];
static __device__ __align__(16) __nv_bfloat16 g_Aq[BATCH * KQ];
static __device__ __align__(16) __nv_bfloat16 g_Bq[(size_t)N_ENT * KB];

// ---------------- helpers --------------------------------------------------
__device__ __forceinline__ float softplusf(float x) {
    return fmaxf(x, 0.f) + log1pf(expf(-fabsf(x)));
}
__device__ __forceinline__ float artanh_clipf(float x) {
    x = fminf(fmaxf(x, -1.f + 1e-5f), 1.f - 1e-5f);
    return 0.5f * (log1pf(x) - log1pf(-x));
}
__device__ __forceinline__ unsigned smem_u32(const void* p) {
    unsigned r;
    asm("{ .reg .u64 t; cvta.to.shared.u64 t, %1; cvt.u32.u64 %0, t; }"
        : "=r"(r) : "l"(p));
    return r;
}

#define CP16(dst, src) \
    asm volatile("cp.async.cg.shared.global [%0], [%1], 16;" \
                 :: "r"(dst), "l"(src) : "memory")
#define CP_COMMIT() asm volatile("cp.async.commit_group;" ::: "memory")
#define CP_WAIT1()  asm volatile("cp.async.wait_group 1;" ::: "memory")

#define LDSM4(r0, r1, r2, r3, addr) \
    asm volatile("ldmatrix.sync.aligned.m8n8.x4.shared.b16 {%0,%1,%2,%3}, [%4];" \
                 : "=r"(r0), "=r"(r1), "=r"(r2), "=r"(r3) : "r"(addr))

#define MMA16816(c, a, b0, b1) \
    asm volatile("mma.sync.aligned.m16n8k16.row.col.f32.bf16.bf16.f32 " \
                 "{%0,%1,%2,%3},{%4,%5,%6,%7},{%8,%9},{%0,%1,%2,%3};" \
                 : "+f"((c)[0]), "+f"((c)[1]), "+f"((c)[2]), "+f"((c)[3]) \
                 : "r"((a)[0]), "r"((a)[1]), "r"((a)[2]), "r"((a)[3]), \
                   "r"(b0), "r"(b1))

// ---------------- fc1 split-K: X = pos[h]*pvw[h]*scale built on the fly ----
__global__ void fc1_split_kernel(const int* __restrict__ x,
                                 const float* __restrict__ pos,
                                 const float* __restrict__ pvw,
                                 const float* __restrict__ W,
                                 float* __restrict__ Cp) {
    const int z = blockIdx.z;
    const int kb = z * (INSZ / NSPLIT), ke = kb + INSZ / NSPLIT;
    __shared__ float Xs[16][32];
    __shared__ float Ws[16][64];
    __shared__ int sh_h[32];
    const int tid = threadIdx.x;
    const int tx = tid & 15, ty = tid >> 4;
    const int bm = blockIdx.y * 32, bn = blockIdx.x * 64;
    float acc[4][4] = {};

    if (tid < 32) sh_h[tid] = x[(bm + tid) * 3];
    __syncthreads();

    const int xl_row = tid & 31, xl_k = (tid >> 5) * 4;
    const int wl_row = tid & 63, wl_k = (tid >> 6) * 8;
    const int hrow = sh_h[xl_row];
    const int ng_w = bn + wl_row;

    for (int k0 = kb; k0 < ke; k0 += 16) {
#pragma unroll
        for (int i = 0; i < 4; i++) {
            int kg = k0 + xl_k + i;
            Xs[xl_k + i][xl_row] = (kg < ke)
                ? pos[(size_t)hrow * INSZ + kg] * pvw[(size_t)hrow * INSZ + kg] * SCALE
                : 0.f;
        }
#pragma unroll
        for (int i = 0; i < 8; i++) {
            int kg = k0 + wl_k + i;
            Ws[wl_k + i][wl_row] = (kg < ke && ng_w < RANKD)
                ? W[(size_t)ng_w * INSZ + kg] : 0.f;
        }
        __syncthreads();
#pragma unroll
        for (int kk = 0; kk < 16; kk++) {
            float a[4], b[4];
#pragma unroll
            for (int i = 0; i < 4; i++) a[i] = Xs[kk][ty * 4 + i];
#pragma unroll
            for (int j = 0; j < 4; j++) b[j] = Ws[kk][tx * 4 + j];
#pragma unroll
            for (int i = 0; i < 4; i++)
#pragma unroll
                for (int j = 0; j < 4; j++) acc[i][j] += a[i] * b[j];
        }
        __syncthreads();
    }
    float* out = Cp + (size_t)z * BATCH * RANKD;
#pragma unroll
    for (int i = 0; i < 4; i++) {
        int mg = bm + ty * 4 + i;
#pragma unroll
        for (int j = 0; j < 4; j++) {
            int ng = bn + tx * 4 + j;
            if (ng < RANKD) out[(size_t)mg * RANKD + ng] = acc[i][j];
        }
    }
}

// ---------------- fc2 split-K: X = sum4(t1p) + fc1_b ; K=500 split 4x125 ---
__global__ void fc2_split_kernel(const float* __restrict__ Xp,
                                 const float* __restrict__ xbias,
                                 const float* __restrict__ W,
                                 float* __restrict__ Cp) {
    const int z = blockIdx.z;
    const int kb = z * (RANKD / NSPLIT), ke = kb + RANKD / NSPLIT;
    __shared__ float Xs[16][32];
    __shared__ float Ws[16][64];
    const int tid = threadIdx.x;
    const int tx = tid & 15, ty = tid >> 4;
    const int bm = blockIdx.y * 32, bn = blockIdx.x * 64;
    float acc[4][4] = {};

    const int xl_row = tid & 31, xl_k = (tid >> 5) * 4;
    const int wl_row = tid & 63, wl_k = (tid >> 6) * 8;
    const int mg_x = bm + xl_row;
    const int ng_w = bn + wl_row;

    for (int k0 = kb; k0 < ke; k0 += 16) {
#pragma unroll
        for (int i = 0; i < 4; i++) {
            int kg = k0 + xl_k + i;
            float v = 0.f;
            if (kg < ke) {
                size_t idx = (size_t)mg_x * RANKD + kg;
                v = Xp[idx] + Xp[idx + (size_t)BATCH * RANKD]
                  + Xp[idx + (size_t)2 * BATCH * RANKD]
                  + Xp[idx + (size_t)3 * BATCH * RANKD] + xbias[kg];
            }
            Xs[xl_k + i][xl_row] = v;
        }
#pragma unroll
        for (int i = 0; i < 8; i++) {
            int kg = k0 + wl_k + i;
            Ws[wl_k + i][wl_row] = (kg < ke && ng_w < RANKD)
                ? W[(size_t)ng_w * RANKD + kg] : 0.f;
        }
        __syncthreads();
#pragma unroll
        for (int kk = 0; kk < 16; kk++) {
            float a[4], b[4];
#pragma unroll
            for (int i = 0; i < 4; i++) a[i] = Xs[kk][ty * 4 + i];
#pragma unroll
            for (int j = 0; j < 4; j++) b[j] = Ws[kk][tx * 4 + j];
#pragma unroll
            for (int i = 0; i < 4; i++)
#pragma unroll
                for (int j = 0; j < 4; j++) acc[i][j] += a[i] * b[j];
        }
        __syncthreads();
    }
    float* out = Cp + (size_t)z * BATCH * RANKD;
#pragma unroll
    for (int i = 0; i < 4; i++) {
        int mg = bm + ty * 4 + i;
#pragma unroll
        for (int j = 0; j < 4; j++) {
            int ng = bn + tx * 4 + j;
            if (ng < RANKD) out[(size_t)mg * RANKD + ng] = acc[i][j];
        }
    }
}

// ---------------- fc3 split-K: X = g_t2 (plain) ; K=500 split 4x125 --------
__global__ void fc3_split_kernel(const float* __restrict__ X,
                                 const float* __restrict__ W,
                                 float* __restrict__ Cp) {
    const int z = blockIdx.z;
    const int kb = z * (RANKD / NSPLIT), ke = kb + RANKD / NSPLIT;
    __shared__ float Xs[16][32];
    __shared__ float Ws[16][64];
    const int tid = threadIdx.x;
    const int tx = tid & 15, ty = tid >> 4;
    const int bm = blockIdx.y * 32, bn = blockIdx.x * 64;
    float acc[4][4] = {};

    const int xl_row = tid & 31, xl_k = (tid >> 5) * 4;
    const int wl_row = tid & 63, wl_k = (tid >> 6) * 8;
    const int mg_x = bm + xl_row;
    const int ng_w = bn + wl_row;

    for (int k0 = kb; k0 < ke; k0 += 16) {
#pragma unroll
        for (int i = 0; i < 4; i++) {
            int kg = k0 + xl_k + i;
            Xs[xl_k + i][xl_row] = (kg < ke) ? X[(size_t)mg_x * RANKD + kg] : 0.f;
        }
#pragma unroll
        for (int i = 0; i < 8; i++) {
            int kg = k0 + wl_k + i;
            Ws[wl_k + i][wl_row] = (kg < ke && ng_w < RANKD)
                ? W[(size_t)ng_w * RANKD + kg] : 0.f;
        }
        __syncthreads();
#pragma unroll
        for (int kk = 0; kk < 16; kk++) {
            float a[4], b[4];
#pragma unroll
            for (int i = 0; i < 4; i++) a[i] = Xs[kk][ty * 4 + i];
#pragma unroll
            for (int j = 0; j < 4; j++) b[j] = Ws[kk][tx * 4 + j];
#pragma unroll
            for (int i = 0; i < 4; i++)
#pragma unroll
                for (int j = 0; j < 4; j++) acc[i][j] += a[i] * b[j];
        }
        __syncthreads();
    }
    float* out = Cp + (size_t)z * BATCH * RANKD;
#pragma unroll
    for (int i = 0; i < 4; i++) {
        int mg = bm + ty * 4 + i;
#pragma unroll
        for (int j = 0; j < 4; j++) {
            int ng = bn + tx * 4 + j;
            if (ng < RANKD) out[(size_t)mg * RANKD + ng] = acc[i][j];
        }
    }
}

// ---------------- LayerNorm: sum 4 partials + fc2_b, normalize -> g_t2 -----
__global__ void ln_sum_kernel(const float* __restrict__ xbias,
                              const float* __restrict__ g,
                              const float* __restrict__ bta) {
    int row = blockIdx.x;
    const size_t base = (size_t)row * RANKD;
    const size_t stride = (size_t)BATCH * RANKD;
    __shared__ float s1[128], s2[128];
    __shared__ float vals[RANKD];
    float sum = 0.f, ss = 0.f;
    for (int d = threadIdx.x; d < RANKD; d += 128) {
        float v = g_t2p[base + d] + g_t2p[base + d + stride]
                + g_t2p[base + d + 2 * stride] + g_t2p[base + d + 3 * stride]
                + xbias[d];
        vals[d] = v;
        sum += v;
        ss += v * v;
    }
    s1[threadIdx.x] = sum;
    s2[threadIdx.x] = ss;
    __syncthreads();
    for (int s = 64; s > 0; s >>= 1) {
        if (threadIdx.x < s) {
            s1[threadIdx.x] += s1[threadIdx.x + s];
            s2[threadIdx.x] += s2[threadIdx.x + s];
        }
        __syncthreads();
    }
    float mu = s1[0] / RANKD;
    float var = s2[0] / RANKD - mu * mu;
    float rstd = rsqrtf(fmaxf(var, 0.f) + 1e-5f);
    for (int d = threadIdx.x; d < RANKD; d += 128)
        g_t2[base + d] = (vals[d] - mu) * rstd * g[d] + bta[d];
}

// ---------------- fused per-batch kernel: writes g_Aq = [hi|lo|hi] ---------
__global__ void fuse_kernel(const int* __restrict__ x, const int* __restrict__ nbrs,
                            const float* __restrict__ emb_e, const float* __restrict__ emb_r,
                            const float* __restrict__ emb1_r, const float* __restrict__ ctxv,
                            const float* __restrict__ nvw,
                            const float* __restrict__ c1_p, const float* __restrict__ c2_p,
                            const float* __restrict__ ab_p,
                            const float* __restrict__ mn_w, const float* __restrict__ mn_b,
                            const float* __restrict__ fc3_b) {
    const int b = blockIdx.x;
    const int tid = threadIdx.x;
    __shared__ int sh_idx[12];
    __shared__ float red[5][128];
    __shared__ float sh_lhs[RANKD];
    __shared__ float sh_rot[RANKD];
    __shared__ float shS[12];

    if (tid == 0) {
        int h = x[b * 3], r = x[b * 3 + 1];
        sh_idx[0] = h;
        sh_idx[1] = r;
        for (int j = 0; j < 5; j++) {
            sh_idx[2 + j] = nbrs[(h * 5 + j) * 2];
            sh_idx[7 + j] = nbrs[(h * 5 + j) * 2 + 1];
        }
    }
    __syncthreads();
    const int h = sh_idx[0], r = sh_idx[1];

    float pj[5] = {0, 0, 0, 0, 0};
    for (int d = tid; d < RANKD; d += 128) {
#pragma unroll
        for (int j = 0; j < 5; j++) {
            int rel = sh_idx[7 + j];
            pj[j] += nvw[rel * RANKD + d] * emb_r[rel * GK + d];
        }
    }
#pragma unroll
    for (int j = 0; j < 5; j++) red[j][tid] = pj[j];
    __syncthreads();
    for (int s = 64; s > 0; s >>= 1) {
        if (tid < s) {
#pragma unroll
            for (int j = 0; j < 5; j++) red[j][tid] += red[j][tid + s];
        }
        __syncthreads();
    }
    if (tid == 0) {
        float l[5], mx = -1e30f;
        for (int j = 0; j < 5; j++) {
            l[j] = red[j][0] * SCALE;
            mx = fmaxf(mx, l[j]);
        }
        float se = 0.f;
        for (int j = 0; j < 5; j++) {
            l[j] = expf(l[j] - mx);
            se += l[j];
        }
        float ab = 0.f;
        for (int j = 0; j < 5; j++) {
            shS[j] = l[j] / se;
            ab += softplusf(ab_p[sh_idx[7 + j]]);
        }
        shS[5] = ab * 0.2f;
        shS[6] = softplusf(mn_w[r] + mn_b[0]);
        shS[7] = sqrtf(softplusf(c1_p[r]));
        shS[8] = sqrtf(softplusf(c2_p[r]));
    }
    __syncthreads();

    float ss = 0.f;
    {
        float ab = shS[5], mn = shS[6];
        const size_t base = (size_t)b * RANKD;
        const size_t stride = (size_t)BATCH * RANKD;
        for (int d = tid; d < RANKD; d += 128) {
            float att = 0.f;
#pragma unroll
            for (int j = 0; j < 5; j++) att += shS[j] * emb_e[sh_idx[2 + j] * GK + d];
            float t3 = g_t3p[base + d] + g_t3p[base + d + stride]
                     + g_t3p[base + d + 2 * stride] + g_t3p[base + d + 3 * stride]
                     + fc3_b[d];
            float v = emb_e[h * GK + d] + ab * att + mn * t3;
            sh_lhs[d] = v;
            ss += v * v;
        }
    }
    red[0][tid] = ss;
    __syncthreads();
    for (int s = 64; s > 0; s >>= 1) {
        if (tid < s) red[0][tid] += red[0][tid + s];
        __syncthreads();
    }
    if (tid == 0) {
        float sc1 = shS[7], sc2 = shS[8];
        float n = sqrtf(red[0][0]);
        float un = fmaxf(n, 1e-15f);
        float t1h = tanhf(sc1 * un);
        float f1 = t1h / (sc1 * un);
        float gn = fmaxf(f1 * n, 1e-15f);
        float mx1 = 0.996f / sc1;
        float pf1 = (gn > mx1) ? (mx1 / gn) : 1.f;
        float h1s = pf1 * f1;
        float yn1 = h1s * n;
        float un2 = fmaxf(yn1, 1e-15f);
        float t2h = tanhf(sc2 * un2);
        float f2 = t2h / (sc2 * un2);
        float gn2 = fmaxf(f2 * yn1, 1e-15f);
        float mx2 = 0.996f / sc2;
        float pf2 = (gn2 > mx2) ? (mx2 / gn2) : 1.f;
        float beta = pf2 * f2;
        float yn2 = beta * yn1;
        float y1 = fmaxf(yn1, 1e-15f);
        float a1 = artanh_clipf(sc1 * y1) / (y1 * sc1);
        float y2 = fmaxf(yn2, 1e-15f);
        float a2 = artanh_clipf(sc2 * y2) / (y2 * sc2);
        shS[9] = h1s;
        shS[10] = a1;
        shS[11] = a2 * beta;
    }
    __syncthreads();

    float pd = 0.f;
    {
        float h1s = shS[9];
        for (int q = tid; q < RANKD / 2; q += 128) {
            float g0 = emb1_r[r * GK + 2 * q];
            float g1 = emb1_r[r * GK + 2 * q + 1];
            float gg = fmaxf(sqrtf(g0 * g0 + g1 * g1), 1e-15f);
            g0 /= gg;
            g1 /= gg;
            float x0 = h1s * sh_lhs[2 * q];
            float x1 = h1s * sh_lhs[2 * q + 1];
            float r0 = g0 * x0 - g1 * x1;
            float r1 = g0 * x1 + g1 * x0;
            sh_rot[2 * q] = r0;
            sh_rot[2 * q + 1] = r1;
            pd += ctxv[r * RANKD + 2 * q] * r0 + ctxv[r * RANKD + 2 * q + 1] * r1;
        }
    }
    red[0][tid] = pd;
    __syncthreads();
    for (int s = 64; s > 0; s >>= 1) {
        if (tid < s) red[0][tid] += red[0][tid + s];
        __syncthreads();
    }
    if (tid == 0) {
        float d0 = red[0][0] * SCALE;
        float s1 = shS[10], s2 = shS[11];
        float l0 = s1 * d0, l1 = s2 * d0, l2 = d0;
        float mx = fmaxf(l0, fmaxf(l1, l2));
        float e0 = expf(l0 - mx), e1 = expf(l1 - mx), e2 = expf(l2 - mx);
        float inv = 1.f / (e0 + e1 + e2);
        shS[0] = (e0 * s1 + e1 * s2 + e2) * inv;
    }
    __syncthreads();

    // Phase D: write A' row directly (hi | lo | hi), bf16, pad tails = 0
    {
        float S = shS[0];
        __nv_bfloat16* dst = g_Aq + (size_t)b * KQ;
        for (int d = tid; d < RANKD; d += 128) {
            float aq = S * sh_rot[d];
            float l1v = emb_e[h * GK + RANKD + d];
            float r0v = emb_r[r * GK + d];
            float rbv = emb_r[r * GK + RANKD + d];
            float A0 = aq * r0v - l1v * rbv;
            float A1 = aq * rbv + l1v * r0v;
            __nv_bfloat16 h0 = __float2bfloat16(A0);
            __nv_bfloat16 h1 = __float2bfloat16(A1);
            __nv_bfloat16 lo0 = __float2bfloat16(A0 - __bfloat162float(h0));
            __nv_bfloat16 lo1 = __float2bfloat16(A1 - __bfloat162float(h1));
            dst[d] = h0;             dst[RANKD + d] = h1;
            dst[1024 + d] = lo0;     dst[1024 + RANKD + d] = lo1;
            dst[2048 + d] = h0;      dst[2048 + RANKD + d] = h1;
        }
        if (tid < 24) {
            __nv_bfloat16 z = __float2bfloat16(0.f);
            dst[1000 + tid] = z;
            dst[2024 + tid] = z;
            dst[3048 + tid] = z;
        }
    }
}

// ---------------- conversion: B' = [hi | lo] bf16 of emb_e -----------------
__global__ void convB_kernel(const float* __restrict__ emb_e) {
    int n = blockIdx.x;
    const float* src = emb_e + (size_t)n * GK;
    __nv_bfloat162* dh = (__nv_bfloat162*)(g_Bq + (size_t)n * KB);
    __nv_bfloat162* dl = dh + 512;
    for (int p = threadIdx.x; p < 512; p += 128) {
        int k = 2 * p;
        float a = (k < GK) ? src[k] : 0.f;
        float b = (k + 1 < GK) ? src[k + 1] : 0.f;
        __nv_bfloat16 ah = __float2bfloat16(a);
        __nv_bfloat16 bh = __float2bfloat16(b);
        __nv_bfloat16 al = __float2bfloat16(a - __bfloat162float(ah));
        __nv_bfloat16 bl = __float2bfloat16(b - __bfloat162float(bh));
        dh[p] = __halves2bfloat162(ah, bh);
        dl[p] = __halves2bfloat162(al, bl);
    }
}

// ---------------- big GEMM via mma.sync bf16 -------------------------------
// R12 winner + single-barrier mainloop ONLY (single variable this round).
#define NSTG      3
#define STG_BYT   32768          /* A 16KB + B 16KB */
#define SMEM_GEMM (NSTG * STG_BYT)
#define KSTAGES   (KQ / 64)      /* 48 */

__global__ void __launch_bounds__(256, 2)
big_gemm_mma(float* __restrict__ C) {
    extern __shared__ __align__(1024) char smem[];
    const unsigned sb = smem_u32(smem);
    const int tid = threadIdx.x;
    const int wid = tid >> 5, lane = tid & 31;
    const int bm = blockIdx.y * 128;
    const int bn = blockIdx.x * 128;
    const int wm = wid >> 2;          // 0..1
    const int wn = wid & 3;           // 0..3

    auto load_stage = [&](int st) {
        const unsigned abase = sb + (unsigned)(st % NSTG) * STG_BYT;
        const unsigned bbase = abase + 16384u;
        const int k0 = st * 64;
        const int bk = (k0 < 1024) ? k0 : k0 - 1024;   // hi.hi | lo.hi | hi.lo
#pragma unroll
        for (int i = 0; i < 4; i++) {
            int q = tid + 256 * i;
            int row = q >> 3, c = q & 7;
            unsigned dst = abase + (unsigned)(row * 128 + ((c ^ (row & 7)) << 4));
            const void* src = g_Aq + (size_t)(bm + row) * KQ + k0 + c * 8;
            CP16(dst, src);
        }
#pragma unroll
        for (int i = 0; i < 4; i++) {
            int q = tid + 256 * i;
            int row = q >> 3, c = q & 7;
            int gr = bn + row;
            if (gr >= N_ENT) gr = 0;
            unsigned dst = bbase + (unsigned)(row * 128 + ((c ^ (row & 7)) << 4));
            const void* src = g_Bq + (size_t)gr * KB + bk + c * 8;
            CP16(dst, src);
        }
    };

    float acc[4][4][4];
#pragma unroll
    for (int i = 0; i < 4; i++)
#pragma unroll
        for (int j = 0; j < 4; j++)
#pragma unroll
            for (int v = 0; v < 4; v++) acc[i][j][v] = 0.f;

    load_stage(0); CP_COMMIT();
    load_stage(1); CP_COMMIT();

    const int a_row_l = lane & 15;
    const int a_ch_l  = lane >> 4;
    const int b_row_l = (lane & 7) + ((lane >> 4) << 3);
    const int b_ch_l  = (lane >> 3) & 1;

    for (int kb = 0; kb < KSTAGES; ++kb) {
        CP_WAIT1();
        __syncthreads();          // orders prev-iter reads before this iter's
                                  // writes into slot (kb+2)%3 == slot(kb-1)
        if (kb + 2 < KSTAGES) load_stage(kb + 2);
        CP_COMMIT();

        const unsigned abase = sb + (unsigned)(kb % NSTG) * STG_BYT;
        const unsigned bbase = abase + 16384u;

#pragma unroll
        for (int k16 = 0; k16 < 4; ++k16) {
            unsigned a[4][4];
#pragma unroll
            for (int fi = 0; fi < 4; ++fi) {
                int row = wm * 64 + fi * 16 + a_row_l;
                int ch = k16 * 2 + a_ch_l;
                unsigned addr = abase + (unsigned)(row * 128 + ((ch ^ (row & 7)) << 4));
                LDSM4(a[fi][0], a[fi][1], a[fi][2], a[fi][3], addr);
            }
            unsigned b[4][2];
#pragma unroll
            for (int bj = 0; bj < 2; ++bj) {
                int row = wn * 32 + bj * 16 + b_row_l;
                int ch = k16 * 2 + b_ch_l;
                unsigned addr = bbase + (unsigned)(row * 128 + ((ch ^ (row & 7)) << 4));
                unsigned r0, r1, r2, r3;
                LDSM4(r0, r1, r2, r3, addr);
                b[2 * bj][0] = r0; b[2 * bj][1] = r1;
                b[2 * bj + 1][0] = r2; b[2 * bj + 1][1] = r3;
            }
#pragma unroll
            for (int fi = 0; fi < 4; ++fi)
#pragma unroll
                for (int fj = 0; fj < 4; ++fj)
                    MMA16816(acc[fi][fj], a[fi], b[fj][0], b[fj][1]);
        }
        // no end barrier: single-barrier pipeline
    }

    // scalar stores (N_ENT odd -> odd rows only 4B-aligned)
#pragma unroll
    for (int fi = 0; fi < 4; ++fi) {
        int r0 = bm + wm * 64 + fi * 16 + (lane >> 2);
        float* crow0 = C + (size_t)r0 * N_ENT;
        float* crow1 = crow0 + (size_t)8 * N_ENT;
#pragma unroll
        for (int fj = 0; fj < 4; ++fj) {
            int col = bn + wn * 32 + fj * 8 + (lane & 3) * 2;
            if (col + 1 < N_ENT) {
                crow0[col]     = acc[fi][fj][0];
                crow0[col + 1] = acc[fi][fj][1];
                crow1[col]     = acc[fi][fj][2];
                crow1[col + 1] = acc[fi][fj][3];
            } else if (col < N_ENT) {
                crow0[col] = acc[fi][fj][0];
                crow1[col] = acc[fi][fj][2];
            }
        }
    }
}

// ---------------- launch ----------------------------------------------------
extern "C" void kernel_launch(void* const* d_in, const int* in_sizes, int n_in,
                              void* d_out, int out_size) {
    const int* x = (const int*)d_in[0];
    const int* neighbors = (const int*)d_in[1];
    const float* position = (const float*)d_in[2];
    const float* emb_e = (const float*)d_in[3];
    const float* emb_r = (const float*)d_in[4];
    const float* emb1_r = (const float*)d_in[5];
    const float* context_vec = (const float*)d_in[6];
    const float* neighbor_vec_w = (const float*)d_in[7];
    const float* position_vec_w = (const float*)d_in[8];
    const float* c1_p = (const float*)d_in[9];
    const float* c2_p = (const float*)d_in[10];
    const float* ab_p = (const float*)d_in[11];
    const float* fc1_w = (const float*)d_in[12];
    const float* fc1_b = (const float*)d_in[13];
    const float* fc2_w = (const float*)d_in[14];
    const float* fc2_b = (const float*)d_in[15];
    const float* fc3_w = (const float*)d_in[16];
    const float* fc3_b = (const float*)d_in[17];
    const float* ln_g = (const float*)d_in[18];
    const float* ln_b = (const float*)d_in[19];
    const float* fc_mn_w = (const float*)d_in[20];
    const float* fc_mn_b = (const float*)d_in[21];
    float* out = (float*)d_out;

    cudaFuncSetAttribute(big_gemm_mma,
                         cudaFuncAttributeMaxDynamicSharedMemorySize, SMEM_GEMM);

    float *p_t1p, *p_t2p, *p_t2, *p_t3p;
    cudaGetSymbolAddress((void**)&p_t1p, g_t1p);
    cudaGetSymbolAddress((void**)&p_t2p, g_t2p);
    cudaGetSymbolAddress((void**)&p_t2, g_t2);
    cudaGetSymbolAddress((void**)&p_t3p, g_t3p);

    // single stream, convB first (fork retired: regressed in R10 and R13)
    convB_kernel<<<N_ENT, 128>>>(emb_e);

    dim3 gsm((RANKD + 63) / 64, BATCH / 32, NSPLIT);
    fc1_split_kernel<<<gsm, 128>>>(x, position, position_vec_w, fc1_w, p_t1p);
    fc2_split_kernel<<<gsm, 128>>>(p_t1p, fc1_b, fc2_w, p_t2p);
    ln_sum_kernel<<<BATCH, 128>>>(fc2_b, ln_g, ln_b);
    fc3_split_kernel<<<gsm, 128>>>(p_t2, fc3_w, p_t3p);

    fuse_kernel<<<BATCH, 128>>>(x, neighbors, emb_e, emb_r, emb1_r, context_vec,
                                neighbor_vec_w, c1_p, c2_p, ab_p, fc_mn_w, fc_mn_b,
                                fc3_b);

    dim3 gbig((N_ENT + 127) / 128, BATCH / 128);
    big_gemm_mma<<<gbig, 256, SMEM_GEMM>>>(out);
}